// round 1
// baseline (speedup 1.0000x reference)
#include <cuda_runtime.h>
#include <math_constants.h>
#include <cstdint>

// Problem constants (fixed by setup_inputs)
#define D_MODEL 1024
#define NHEAD   16
#define HDIM    64

// ---------------- scratch (no allocations allowed) ----------------
__device__ float g_Q[4096 * 1024];
__device__ float g_K[4096 * 1024];
__device__ float g_V[4096 * 1024];
__device__ float g_Oa[4096 * 1024];

// ---------------- GEMM: C[M,N] = A[M,K] @ B[N,K]^T  (NT, both K-major) ----------------
// 128x128 tile, BK=16, 256 threads, 8x8 microtile.
#define GT   128
#define GK   16
#define GPAD 132

__global__ __launch_bounds__(256) void gemm3_nt(
    const float* __restrict__ A,
    const float* __restrict__ W0, const float* __restrict__ W1, const float* __restrict__ W2,
    float* __restrict__ C0, float* __restrict__ C1, float* __restrict__ C2,
    int M, int N, int K)
{
    const float* __restrict__ B = (blockIdx.z == 0) ? W0 : (blockIdx.z == 1) ? W1 : W2;
    float* __restrict__ C       = (blockIdx.z == 0) ? C0 : (blockIdx.z == 1) ? C1 : C2;

    __shared__ float sA[GK * GPAD];
    __shared__ float sB[GK * GPAD];

    const int t  = threadIdx.x;
    const int tx = t & 15;        // 0..15 -> 8 cols each
    const int ty = t >> 4;        // 0..15 -> 8 rows each
    const int m0 = blockIdx.y * GT;
    const int n0 = blockIdx.x * GT;

    float acc[8][8];
#pragma unroll
    for (int i = 0; i < 8; i++)
#pragma unroll
        for (int j = 0; j < 8; j++) acc[i][j] = 0.f;

    for (int k0 = 0; k0 < K; k0 += GK) {
        // load A tile (128 x 16) and B tile (128 x 16), transposed into [k][m]
#pragma unroll
        for (int q = 0; q < 2; q++) {
            int fi = t + 256 * q;          // 0..511 float4 index
            int r  = fi >> 2;              // 0..127
            int c4 = fi & 3;               // 0..3  (float4 within the 16-wide K panel)
            float4 va = *(const float4*)(A + (size_t)(m0 + r) * K + k0 + c4 * 4);
            float4 vb = *(const float4*)(B + (size_t)(n0 + r) * K + k0 + c4 * 4);
            sA[(c4 * 4 + 0) * GPAD + r] = va.x;
            sA[(c4 * 4 + 1) * GPAD + r] = va.y;
            sA[(c4 * 4 + 2) * GPAD + r] = va.z;
            sA[(c4 * 4 + 3) * GPAD + r] = va.w;
            sB[(c4 * 4 + 0) * GPAD + r] = vb.x;
            sB[(c4 * 4 + 1) * GPAD + r] = vb.y;
            sB[(c4 * 4 + 2) * GPAD + r] = vb.z;
            sB[(c4 * 4 + 3) * GPAD + r] = vb.w;
        }
        __syncthreads();

#pragma unroll
        for (int k = 0; k < GK; k++) {
            float a[8], b[8];
            *(float4*)(a)     = *(const float4*)&sA[k * GPAD + ty * 8];
            *(float4*)(a + 4) = *(const float4*)&sA[k * GPAD + ty * 8 + 4];
            *(float4*)(b)     = *(const float4*)&sB[k * GPAD + tx * 8];
            *(float4*)(b + 4) = *(const float4*)&sB[k * GPAD + tx * 8 + 4];
#pragma unroll
            for (int i = 0; i < 8; i++)
#pragma unroll
                for (int j = 0; j < 8; j++)
                    acc[i][j] += a[i] * b[j];
        }
        __syncthreads();
    }

#pragma unroll
    for (int i = 0; i < 8; i++) {
        float* cp = C + (size_t)(m0 + ty * 8 + i) * N + n0 + tx * 8;
        float4 v0 = make_float4(acc[i][0], acc[i][1], acc[i][2], acc[i][3]);
        float4 v1 = make_float4(acc[i][4], acc[i][5], acc[i][6], acc[i][7]);
        ((float4*)cp)[0] = v0;
        ((float4*)cp)[1] = v1;
    }
}

// ---------------- Flash attention (fp32, online softmax) ----------------
// 64 q-rows x 64 k-cols tiles, Hd=64. 256 threads: 4 threads per q-row.
// Shared: Qs/Ks/Vs stride 68 (float4-aligned, conflict-free), Ps stride 65.
#define FSTR 68
#define PSTR 65
#define FLASH_SMEM ((3 * 64 * FSTR + 64 * PSTR) * 4)

__global__ __launch_bounds__(256) void flash_fwd(
    const float* __restrict__ Q, const float* __restrict__ K, const float* __restrict__ V,
    float* __restrict__ O, const int* __restrict__ causalp, int S)
{
    extern __shared__ float sm[];
    float* Qs = sm;                    // 64 x 68
    float* Ks = Qs + 64 * FSTR;        // 64 x 68
    float* Vs = Ks + 64 * FSTR;        // 64 x 68
    float* Ps = Vs + 64 * FSTR;        // 64 x 65

    const int qt = blockIdx.x;
    const int h  = blockIdx.y;
    const int b  = blockIdx.z;
    const int t   = threadIdx.x;
    const int row = t >> 2;            // q-row within tile (0..63)
    const int sub = t & 3;             // column quarter (0..3)
    const int causal = causalp[0];

    const size_t base = (size_t)b * S * D_MODEL + h * HDIM;
    const int q0 = qt * 64;

    // Load Q tile, pre-scaled by 1/sqrt(Hd) = 0.125
#pragma unroll
    for (int q = 0; q < 4; q++) {
        int fi = t + 256 * q;          // 0..1023 float4s
        int r  = fi >> 4;              // 0..63
        int c4 = fi & 15;              // 0..15
        float4 v = *(const float4*)(Q + base + (size_t)(q0 + r) * D_MODEL + c4 * 4);
        float* dst = &Qs[r * FSTR + c4 * 4];
        dst[0] = v.x * 0.125f; dst[1] = v.y * 0.125f;
        dst[2] = v.z * 0.125f; dst[3] = v.w * 0.125f;
    }

    float o[16];
#pragma unroll
    for (int i = 0; i < 16; i++) o[i] = 0.f;
    float mrun = -CUDART_INF_F;
    float lrun = 0.f;

    const int nkt = causal ? (qt + 1) : (S >> 6);

    for (int kt = 0; kt < nkt; kt++) {
        const int k0 = kt * 64;
        // Load K and V tiles
#pragma unroll
        for (int q = 0; q < 4; q++) {
            int fi = t + 256 * q;
            int r  = fi >> 4;
            int c4 = fi & 15;
            size_t goff = base + (size_t)(k0 + r) * D_MODEL + c4 * 4;
            float4 kv = *(const float4*)(K + goff);
            float4 vv = *(const float4*)(V + goff);
            float* dk = &Ks[r * FSTR + c4 * 4];
            float* dv = &Vs[r * FSTR + c4 * 4];
            dk[0] = kv.x; dk[1] = kv.y; dk[2] = kv.z; dk[3] = kv.w;
            dv[0] = vv.x; dv[1] = vv.y; dv[2] = vv.z; dv[3] = vv.w;
        }
        __syncthreads();

        // Scores: s[jj] = q_row . k_(sub*16+jj)   (already scaled via Q)
        float s[16];
#pragma unroll
        for (int jj = 0; jj < 16; jj++) s[jj] = 0.f;
#pragma unroll
        for (int d4 = 0; d4 < 16; d4++) {
            float4 q4 = *(const float4*)&Qs[row * FSTR + d4 * 4];
#pragma unroll
            for (int jj = 0; jj < 16; jj++) {
                float4 k4 = *(const float4*)&Ks[(sub * 16 + jj) * FSTR + d4 * 4];
                s[jj] += q4.x * k4.x + q4.y * k4.y + q4.z * k4.z + q4.w * k4.w;
            }
        }

        // Causal mask (only fires on the diagonal tile)
        if (causal && (k0 + 63 > q0 + row)) {
#pragma unroll
            for (int jj = 0; jj < 16; jj++) {
                int kg = k0 + sub * 16 + jj;
                if (kg > q0 + row) s[jj] = -CUDART_INF_F;
            }
        }

        // Online softmax update (4 threads per row; width-4 shuffles)
        float mloc = s[0];
#pragma unroll
        for (int jj = 1; jj < 16; jj++) mloc = fmaxf(mloc, s[jj]);
        mloc = fmaxf(mloc, __shfl_xor_sync(0xffffffffu, mloc, 1, 4));
        mloc = fmaxf(mloc, __shfl_xor_sync(0xffffffffu, mloc, 2, 4));
        float mnew = fmaxf(mrun, mloc);
        float corr = __expf(mrun - mnew);

        float lsum = 0.f;
#pragma unroll
        for (int jj = 0; jj < 16; jj++) {
            float p = __expf(s[jj] - mnew);
            Ps[row * PSTR + sub * 16 + jj] = p;
            lsum += p;
        }
        lsum += __shfl_xor_sync(0xffffffffu, lsum, 1, 4);
        lsum += __shfl_xor_sync(0xffffffffu, lsum, 2, 4);
        lrun = lrun * corr + lsum;
        mrun = mnew;
#pragma unroll
        for (int dd = 0; dd < 16; dd++) o[dd] *= corr;

        __syncwarp();

        // o[d] += sum_j P[row][j] * V[j][d]  (thread owns d = sub*16 .. +15)
#pragma unroll 8
        for (int j = 0; j < 64; j++) {
            float p = Ps[row * PSTR + j];
            const float* vp = &Vs[j * FSTR + sub * 16];
            float4 v0 = ((const float4*)vp)[0];
            float4 v1 = ((const float4*)vp)[1];
            float4 v2 = ((const float4*)vp)[2];
            float4 v3 = ((const float4*)vp)[3];
            o[0]  += p * v0.x; o[1]  += p * v0.y; o[2]  += p * v0.z; o[3]  += p * v0.w;
            o[4]  += p * v1.x; o[5]  += p * v1.y; o[6]  += p * v1.z; o[7]  += p * v1.w;
            o[8]  += p * v2.x; o[9]  += p * v2.y; o[10] += p * v2.z; o[11] += p * v2.w;
            o[12] += p * v3.x; o[13] += p * v3.y; o[14] += p * v3.z; o[15] += p * v3.w;
        }
        __syncthreads();   // protect Ks/Vs before next tile's overwrite
    }

    const float inv = 1.f / lrun;
    float* op = O + base + (size_t)(q0 + row) * D_MODEL + sub * 16;
    float4 r0 = make_float4(o[0] * inv,  o[1] * inv,  o[2] * inv,  o[3] * inv);
    float4 r1 = make_float4(o[4] * inv,  o[5] * inv,  o[6] * inv,  o[7] * inv);
    float4 r2 = make_float4(o[8] * inv,  o[9] * inv,  o[10] * inv, o[11] * inv);
    float4 r3 = make_float4(o[12] * inv, o[13] * inv, o[14] * inv, o[15] * inv);
    ((float4*)op)[0] = r0;
    ((float4*)op)[1] = r1;
    ((float4*)op)[2] = r2;
    ((float4*)op)[3] = r3;
}

// ---------------- launch ----------------
extern "C" void kernel_launch(void* const* d_in, const int* in_sizes, int n_in,
                              void* d_out, int out_size)
{
    const float* x  = (const float*)d_in[0];
    const float* Wq = (const float*)d_in[1];
    const float* Wk = (const float*)d_in[2];
    const float* Wv = (const float*)d_in[3];
    const float* Wo = (const float*)d_in[4];
    const int*   causal = (const int*)d_in[5];

    const int BS = in_sizes[0] / D_MODEL;   // B*S = 4096
    const int S  = 2048;
    const int B  = BS / S;

    float *qb, *kb, *vb, *ob;
    cudaGetSymbolAddress((void**)&qb, g_Q);
    cudaGetSymbolAddress((void**)&kb, g_K);
    cudaGetSymbolAddress((void**)&vb, g_V);
    cudaGetSymbolAddress((void**)&ob, g_Oa);

    // Q/K/V projections: [BS,1024] = x @ W^T, fused into one launch (z = which W)
    dim3 gqkv(D_MODEL / GT, BS / GT, 3);
    gemm3_nt<<<gqkv, 256>>>(x, Wq, Wk, Wv, qb, kb, vb, BS, D_MODEL, D_MODEL);

    // Flash attention
    cudaFuncSetAttribute(flash_fwd, cudaFuncAttributeMaxDynamicSharedMemorySize, FLASH_SMEM);
    dim3 gfl(S / 64, NHEAD, B);
    flash_fwd<<<gfl, 256, FLASH_SMEM>>>(qb, kb, vb, ob, causal, S);

    // Output projection: out = attn_out @ Wo^T
    dim3 go(D_MODEL / GT, BS / GT, 1);
    gemm3_nt<<<go, 256>>>(ob, Wo, Wo, Wo, (float*)d_out, (float*)d_out, (float*)d_out,
                          BS, D_MODEL, D_MODEL);
}

// round 2
// speedup vs baseline: 2.8243x; 2.8243x over previous
#include <cuda_runtime.h>
#include <math_constants.h>
#include <cstdint>

// Problem constants (fixed by setup_inputs)
#define D_MODEL 1024
#define NHEAD   16
#define HDIM    64

// ---------------- scratch (no allocations allowed) ----------------
__device__ float g_Q[4096 * 1024];
__device__ float g_K[4096 * 1024];
__device__ float g_V[4096 * 1024];
__device__ float g_Oa[4096 * 1024];

// ---------------- GEMM: C[M,N] = A[M,K] @ B[N,K]^T  (NT, both K-major) ----------------
// 128x128 tile, BK=16, 256 threads, 8x8 microtile.  (At the 3-reg FFMA roofline.)
#define GT   128
#define GK   16
#define GPAD 132

__global__ __launch_bounds__(256) void gemm3_nt(
    const float* __restrict__ A,
    const float* __restrict__ W0, const float* __restrict__ W1, const float* __restrict__ W2,
    float* __restrict__ C0, float* __restrict__ C1, float* __restrict__ C2,
    int M, int N, int K)
{
    const float* __restrict__ B = (blockIdx.z == 0) ? W0 : (blockIdx.z == 1) ? W1 : W2;
    float* __restrict__ C       = (blockIdx.z == 0) ? C0 : (blockIdx.z == 1) ? C1 : C2;

    __shared__ float sA[GK * GPAD];
    __shared__ float sB[GK * GPAD];

    const int t  = threadIdx.x;
    const int tx = t & 15;
    const int ty = t >> 4;
    const int m0 = blockIdx.y * GT;
    const int n0 = blockIdx.x * GT;

    float acc[8][8];
#pragma unroll
    for (int i = 0; i < 8; i++)
#pragma unroll
        for (int j = 0; j < 8; j++) acc[i][j] = 0.f;

    for (int k0 = 0; k0 < K; k0 += GK) {
#pragma unroll
        for (int q = 0; q < 2; q++) {
            int fi = t + 256 * q;
            int r  = fi >> 2;
            int c4 = fi & 3;
            float4 va = *(const float4*)(A + (size_t)(m0 + r) * K + k0 + c4 * 4);
            float4 vb = *(const float4*)(B + (size_t)(n0 + r) * K + k0 + c4 * 4);
            sA[(c4 * 4 + 0) * GPAD + r] = va.x;
            sA[(c4 * 4 + 1) * GPAD + r] = va.y;
            sA[(c4 * 4 + 2) * GPAD + r] = va.z;
            sA[(c4 * 4 + 3) * GPAD + r] = va.w;
            sB[(c4 * 4 + 0) * GPAD + r] = vb.x;
            sB[(c4 * 4 + 1) * GPAD + r] = vb.y;
            sB[(c4 * 4 + 2) * GPAD + r] = vb.z;
            sB[(c4 * 4 + 3) * GPAD + r] = vb.w;
        }
        __syncthreads();

#pragma unroll
        for (int k = 0; k < GK; k++) {
            float a[8], b[8];
            *(float4*)(a)     = *(const float4*)&sA[k * GPAD + ty * 8];
            *(float4*)(a + 4) = *(const float4*)&sA[k * GPAD + ty * 8 + 4];
            *(float4*)(b)     = *(const float4*)&sB[k * GPAD + tx * 8];
            *(float4*)(b + 4) = *(const float4*)&sB[k * GPAD + tx * 8 + 4];
#pragma unroll
            for (int i = 0; i < 8; i++)
#pragma unroll
                for (int j = 0; j < 8; j++)
                    acc[i][j] += a[i] * b[j];
        }
        __syncthreads();
    }

#pragma unroll
    for (int i = 0; i < 8; i++) {
        float* cp = C + (size_t)(m0 + ty * 8 + i) * N + n0 + tx * 8;
        ((float4*)cp)[0] = make_float4(acc[i][0], acc[i][1], acc[i][2], acc[i][3]);
        ((float4*)cp)[1] = make_float4(acc[i][4], acc[i][5], acc[i][6], acc[i][7]);
    }
}

// ---------------- Flash attention v2 (fp32, register-blocked outer products) ----------------
// Tile: 128 q-rows x 64 k-cols, Hd=64. 512 threads, each owns a 4x4 microtile.
// Qs/Ps stored q-minor (stride 132), Ks d-major (stride 68), Vs row-major (stride 68).
#define FQT  128
#define FKT  64
#define QSTR 132
#define KSTR 68
#define FLASH_SMEM ((2 * 64 * QSTR + 2 * 64 * KSTR) * 4)   // 102400 B

__global__ __launch_bounds__(512) void flash_fwd2(
    const float* __restrict__ Q, const float* __restrict__ K, const float* __restrict__ V,
    float* __restrict__ O, const int* __restrict__ causalp, int S)
{
    extern __shared__ float sm[];
    float* Qs = sm;                      // [64 d][132]  (q-minor)
    float* Ks = Qs + 64 * QSTR;          // [64 d][68]   (k-minor)
    float* Vs = Ks + 64 * KSTR;          // [64 j][68]   (d-minor, row-major)
    float* Ps = Vs + 64 * KSTR;          // [64 j][132]  (q-minor)

    const int qt = blockIdx.x;
    const int h  = blockIdx.y;
    const int b  = blockIdx.z;
    const int t  = threadIdx.x;
    const int tx = t & 15;               // k-col / d-col quarter  (16 x 4 = 64)
    const int ty = t >> 4;               // q-row quarter          (32 x 4 = 128)
    const int causal = causalp[0];

    const size_t base = (size_t)b * S * D_MODEL + h * HDIM;
    const int q0 = qt * FQT;

    // ---- load Q tile (128 x 64), pre-scaled by 1/8, transposed to d-major ----
#pragma unroll
    for (int q = 0; q < 4; q++) {
        int fi = t + 512 * q;            // 0..2047 float4s
        int r  = fi >> 4;                // 0..127 token
        int c4 = fi & 15;                // 0..15  -> d = c4*4
        float4 v = *(const float4*)(Q + base + (size_t)(q0 + r) * D_MODEL + c4 * 4);
        Qs[(c4 * 4 + 0) * QSTR + r] = v.x * 0.125f;
        Qs[(c4 * 4 + 1) * QSTR + r] = v.y * 0.125f;
        Qs[(c4 * 4 + 2) * QSTR + r] = v.z * 0.125f;
        Qs[(c4 * 4 + 3) * QSTR + r] = v.w * 0.125f;
    }

    float o[4][4];
#pragma unroll
    for (int i = 0; i < 4; i++)
#pragma unroll
        for (int j = 0; j < 4; j++) o[i][j] = 0.f;
    float mrun[4], lrun[4];
#pragma unroll
    for (int i = 0; i < 4; i++) { mrun[i] = -CUDART_INF_F; lrun[i] = 0.f; }

    const int ntot = S >> 6;
    const int nkt  = causal ? min(ntot, 2 * qt + 2) : ntot;

    // prefetch registers for K/V tiles (2 float4 each per thread)
    const int pr0 = t >> 4;              // token row for this thread's chunk 0
    const int pc0 = t & 15;
    float4 kreg[2], vreg[2];

    // prefetch tile 0
    {
        size_t g0 = base + (size_t)(pr0) * D_MODEL + pc0 * 4;           // fi = t
        size_t g1 = base + (size_t)(pr0 + 32) * D_MODEL + pc0 * 4;      // fi = t + 512
        kreg[0] = *(const float4*)(K + g0);
        vreg[0] = *(const float4*)(V + g0);
        kreg[1] = *(const float4*)(K + g1);
        vreg[1] = *(const float4*)(V + g1);
    }

    for (int kt = 0; kt < nkt; kt++) {
        const int k0 = kt * FKT;

        // ---- stage prefetched K (transposed to d-major) and V (row-major) ----
#pragma unroll
        for (int q = 0; q < 2; q++) {
            int r  = pr0 + 32 * q;       // 0..63 token
            int d0 = pc0 * 4;
            Ks[(d0 + 0) * KSTR + r] = (q ? kreg[1].x : kreg[0].x);
            Ks[(d0 + 1) * KSTR + r] = (q ? kreg[1].y : kreg[0].y);
            Ks[(d0 + 2) * KSTR + r] = (q ? kreg[1].z : kreg[0].z);
            Ks[(d0 + 3) * KSTR + r] = (q ? kreg[1].w : kreg[0].w);
            *(float4*)&Vs[r * KSTR + d0] = (q ? vreg[1] : vreg[0]);
        }
        __syncthreads();

        // prefetch next tile while computing
        if (kt + 1 < nkt) {
            size_t g0 = base + (size_t)(k0 + FKT + pr0) * D_MODEL + pc0 * 4;
            size_t g1 = base + (size_t)(k0 + FKT + pr0 + 32) * D_MODEL + pc0 * 4;
            kreg[0] = *(const float4*)(K + g0);
            vreg[0] = *(const float4*)(V + g0);
            kreg[1] = *(const float4*)(K + g1);
            vreg[1] = *(const float4*)(V + g1);
        }

        // ---- S = Q K^T  (outer product over d) ----
        float s[4][4];
#pragma unroll
        for (int i = 0; i < 4; i++)
#pragma unroll
            for (int j = 0; j < 4; j++) s[i][j] = 0.f;

#pragma unroll 8
        for (int d = 0; d < 64; d++) {
            float4 a  = *(const float4*)&Qs[d * QSTR + ty * 4];
            float4 bb = *(const float4*)&Ks[d * KSTR + tx * 4];
            s[0][0] += a.x * bb.x; s[0][1] += a.x * bb.y; s[0][2] += a.x * bb.z; s[0][3] += a.x * bb.w;
            s[1][0] += a.y * bb.x; s[1][1] += a.y * bb.y; s[1][2] += a.y * bb.z; s[1][3] += a.y * bb.w;
            s[2][0] += a.z * bb.x; s[2][1] += a.z * bb.y; s[2][2] += a.z * bb.z; s[2][3] += a.z * bb.w;
            s[3][0] += a.w * bb.x; s[3][1] += a.w * bb.y; s[3][2] += a.w * bb.z; s[3][3] += a.w * bb.w;
        }

        // ---- causal mask (only fires near the diagonal) ----
        if (causal && (k0 + FKT - 1 > q0 + ty * 4)) {
#pragma unroll
            for (int i = 0; i < 4; i++) {
                int qg = q0 + ty * 4 + i;
#pragma unroll
                for (int j = 0; j < 4; j++) {
                    if (k0 + tx * 4 + j > qg) s[i][j] = -CUDART_INF_F;
                }
            }
        }

        // ---- online softmax (rows distributed over 16 tx-threads; width-16 shfl) ----
#pragma unroll
        for (int i = 0; i < 4; i++) {
            float mloc = fmaxf(fmaxf(s[i][0], s[i][1]), fmaxf(s[i][2], s[i][3]));
            mloc = fmaxf(mloc, __shfl_xor_sync(0xffffffffu, mloc, 1, 16));
            mloc = fmaxf(mloc, __shfl_xor_sync(0xffffffffu, mloc, 2, 16));
            mloc = fmaxf(mloc, __shfl_xor_sync(0xffffffffu, mloc, 4, 16));
            mloc = fmaxf(mloc, __shfl_xor_sync(0xffffffffu, mloc, 8, 16));
            float mnew = fmaxf(mrun[i], mloc);
            float corr = __expf(mrun[i] - mnew);
            float p0 = __expf(s[i][0] - mnew);
            float p1 = __expf(s[i][1] - mnew);
            float p2 = __expf(s[i][2] - mnew);
            float p3 = __expf(s[i][3] - mnew);
            s[i][0] = p0; s[i][1] = p1; s[i][2] = p2; s[i][3] = p3;
            float ls = p0 + p1 + p2 + p3;
            ls += __shfl_xor_sync(0xffffffffu, ls, 1, 16);
            ls += __shfl_xor_sync(0xffffffffu, ls, 2, 16);
            ls += __shfl_xor_sync(0xffffffffu, ls, 4, 16);
            ls += __shfl_xor_sync(0xffffffffu, ls, 8, 16);
            lrun[i] = lrun[i] * corr + ls;
            mrun[i] = mnew;
            o[i][0] *= corr; o[i][1] *= corr; o[i][2] *= corr; o[i][3] *= corr;
        }

        // ---- store P transposed: Ps[k-col][q-row] ----
#pragma unroll
        for (int j = 0; j < 4; j++) {
            *(float4*)&Ps[(tx * 4 + j) * QSTR + ty * 4] =
                make_float4(s[0][j], s[1][j], s[2][j], s[3][j]);
        }
        __syncthreads();

        // ---- O += P V  (outer product over j) ----
#pragma unroll 8
        for (int j = 0; j < 64; j++) {
            float4 a  = *(const float4*)&Ps[j * QSTR + ty * 4];
            float4 v4 = *(const float4*)&Vs[j * KSTR + tx * 4];
            o[0][0] += a.x * v4.x; o[0][1] += a.x * v4.y; o[0][2] += a.x * v4.z; o[0][3] += a.x * v4.w;
            o[1][0] += a.y * v4.x; o[1][1] += a.y * v4.y; o[1][2] += a.y * v4.z; o[1][3] += a.y * v4.w;
            o[2][0] += a.z * v4.x; o[2][1] += a.z * v4.y; o[2][2] += a.z * v4.z; o[2][3] += a.z * v4.w;
            o[3][0] += a.w * v4.x; o[3][1] += a.w * v4.y; o[3][2] += a.w * v4.z; o[3][3] += a.w * v4.w;
        }
        __syncthreads();   // protect Ks/Vs/Ps before next tile's overwrite
    }

    // ---- epilogue ----
#pragma unroll
    for (int i = 0; i < 4; i++) {
        float inv = 1.f / lrun[i];
        float* op = O + base + (size_t)(q0 + ty * 4 + i) * D_MODEL + tx * 4;
        *(float4*)op = make_float4(o[i][0] * inv, o[i][1] * inv, o[i][2] * inv, o[i][3] * inv);
    }
}

// ---------------- launch ----------------
extern "C" void kernel_launch(void* const* d_in, const int* in_sizes, int n_in,
                              void* d_out, int out_size)
{
    const float* x  = (const float*)d_in[0];
    const float* Wq = (const float*)d_in[1];
    const float* Wk = (const float*)d_in[2];
    const float* Wv = (const float*)d_in[3];
    const float* Wo = (const float*)d_in[4];
    const int*   causal = (const int*)d_in[5];

    const int BS = in_sizes[0] / D_MODEL;   // B*S = 4096
    const int S  = 2048;
    const int B  = BS / S;

    float *qb, *kb, *vb, *ob;
    cudaGetSymbolAddress((void**)&qb, g_Q);
    cudaGetSymbolAddress((void**)&kb, g_K);
    cudaGetSymbolAddress((void**)&vb, g_V);
    cudaGetSymbolAddress((void**)&ob, g_Oa);

    // Q/K/V projections: [BS,1024] = x @ W^T, fused into one launch (z = which W)
    dim3 gqkv(D_MODEL / GT, BS / GT, 3);
    gemm3_nt<<<gqkv, 256>>>(x, Wq, Wk, Wv, qb, kb, vb, BS, D_MODEL, D_MODEL);

    // Flash attention v2
    cudaFuncSetAttribute(flash_fwd2, cudaFuncAttributeMaxDynamicSharedMemorySize, FLASH_SMEM);
    dim3 gfl(S / FQT, NHEAD, B);
    flash_fwd2<<<gfl, 512, FLASH_SMEM>>>(qb, kb, vb, ob, causal, S);

    // Output projection: out = attn_out @ Wo^T
    dim3 go(D_MODEL / GT, BS / GT, 1);
    gemm3_nt<<<go, 256>>>(ob, Wo, Wo, Wo, (float*)d_out, (float*)d_out, (float*)d_out,
                          BS, D_MODEL, D_MODEL);
}

// round 9
// speedup vs baseline: 3.9350x; 1.3932x over previous
#include <cuda_runtime.h>
#include <cuda_bf16.h>
#include <math_constants.h>
#include <cstdint>

// Problem constants (fixed by setup_inputs)
#define D_MODEL 1024
#define NHEAD   16
#define HDIM    64
#define KCAT    3072          // 3 * D_MODEL (bf16-split: A=[hi,hi,lo], W=[hi,lo,hi])

// ---------------- scratch (no allocations allowed) ----------------
__device__ float g_Q[4096 * 1024];
__device__ float g_K[4096 * 1024];
__device__ float g_V[4096 * 1024];
__device__ float g_Oa[4096 * 1024];
__device__ __nv_bfloat16 g_Xcat[4096 * KCAT];
__device__ __nv_bfloat16 g_Wcat[4096 * KCAT];   // 4 weights stacked (q,k,v,o)
__device__ __nv_bfloat16 g_Ocat[4096 * KCAT];

// =================== small PTX helpers (all plain sm_80/90 features) ===================
__device__ __forceinline__ uint32_t smem_u32(const void* p) {
    uint32_t a;
    asm("{ .reg .u64 t; cvta.to.shared.u64 t, %1; cvt.u32.u64 %0, t; }" : "=r"(a) : "l"(p));
    return a;
}
__device__ __forceinline__ void cp16(uint32_t dst, const void* src) {
    asm volatile("cp.async.cg.shared.global [%0], [%1], 16;" :: "r"(dst), "l"(src) : "memory");
}
__device__ __forceinline__ void ldm_x4(uint32_t* r, uint32_t addr) {
    asm volatile("ldmatrix.sync.aligned.m8n8.x4.shared.b16 {%0,%1,%2,%3}, [%4];"
                 : "=r"(r[0]), "=r"(r[1]), "=r"(r[2]), "=r"(r[3]) : "r"(addr));
}
__device__ __forceinline__ void mma16816(float* d, const uint32_t* a, const uint32_t* b) {
    asm volatile(
        "mma.sync.aligned.m16n8k16.row.col.f32.bf16.bf16.f32 "
        "{%0,%1,%2,%3}, {%4,%5,%6,%7}, {%8,%9}, {%0,%1,%2,%3};"
        : "+f"(d[0]), "+f"(d[1]), "+f"(d[2]), "+f"(d[3])
        : "r"(a[0]), "r"(a[1]), "r"(a[2]), "r"(a[3]), "r"(b[0]), "r"(b[1]));
}

// =================== fp32 -> bf16 hi/lo split-cat conversion ===================
__device__ __forceinline__ uint32_t pk2(__nv_bfloat16 a, __nv_bfloat16 b) {
    return (uint32_t)__bfloat16_as_ushort(a) | ((uint32_t)__bfloat16_as_ushort(b) << 16);
}
// src [rows,1024] fp32 -> dst [rows,3072] bf16.  mode 0 (A): [hi,hi,lo]; mode 1 (W): [hi,lo,hi]
__global__ __launch_bounds__(256) void convert_split(
    const float* __restrict__ src, __nv_bfloat16* __restrict__ dst, int mode)
{
    int i4 = blockIdx.x * blockDim.x + threadIdx.x;  // float4 index; row = i4/256
    float4 v = ((const float4*)src)[i4];
    int row = i4 >> 8;
    int c   = (i4 & 255) * 4;
    float f[4] = {v.x, v.y, v.z, v.w};
    __nv_bfloat16 h[4], l[4];
#pragma unroll
    for (int i = 0; i < 4; i++) {
        h[i] = __float2bfloat16(f[i]);
        l[i] = __float2bfloat16(f[i] - __bfloat162float(h[i]));
    }
    uint2 hp = make_uint2(pk2(h[0], h[1]), pk2(h[2], h[3]));
    uint2 lp = make_uint2(pk2(l[0], l[1]), pk2(l[2], l[3]));
    size_t b = (size_t)row * KCAT + c;
    *(uint2*)&dst[b]        = hp;                       // seg 0: hi
    *(uint2*)&dst[b + 1024] = mode ? lp : hp;           // seg 1
    *(uint2*)&dst[b + 2048] = mode ? hp : lp;           // seg 2
}

// =================== mma.sync bf16 GEMM: C[M,1024] = A_cat[M,3072] @ W_cat^T ===================
// 128x128 tile, BK=32, 256 threads (8 warps in 4x2: each 32 rows x 64 cols).
// Double-buffered cp.async. Rows padded to 40 bf16 (80B) -> conflict-free ldmatrix.
#define BK    32
#define ASTR  40
#define NSTG  2

__global__ __launch_bounds__(256) void gemm_mma(
    const __nv_bfloat16* __restrict__ A, const __nv_bfloat16* __restrict__ W,
    float* __restrict__ C0, float* __restrict__ C1, float* __restrict__ C2,
    int wbase)
{
    __shared__ __nv_bfloat16 sA[NSTG][128 * ASTR];
    __shared__ __nv_bfloat16 sB[NSTG][128 * ASTR];

    float* __restrict__ C = (blockIdx.z == 0) ? C0 : (blockIdx.z == 1) ? C1 : C2;
    const int m0 = blockIdx.y * 128;
    const int n0 = blockIdx.x * 128;
    const int wrow0 = wbase + blockIdx.z * 1024 + n0;

    const int t    = threadIdx.x;
    const int lane = t & 31;
    const int wid  = t >> 5;
    const int wm   = wid & 3;          // 4 warps down: 32 rows each
    const int wn   = wid >> 2;         // 2 warps across: 64 cols each

    const uint32_t sAb = smem_u32(sA);
    const uint32_t sBb = smem_u32(sB);

    // per-thread load coordinates: chunks t and t+256 of 512 (each 8 bf16 = 16B)
    const int r0c = t >> 2, c0c = (t & 3) * 8;          // chunk t
    const int r1c = (t + 256) >> 2, c1c = ((t + 256) & 3) * 8;

    float acc[2][8][4];
#pragma unroll
    for (int mt = 0; mt < 2; mt++)
#pragma unroll
        for (int nt = 0; nt < 8; nt++)
#pragma unroll
            for (int q = 0; q < 4; q++) acc[mt][nt][q] = 0.f;

    const int nk = KCAT / BK;          // 96

    // ---- stage 0 prologue ----
    {
        cp16(sAb + (uint32_t)(r0c * ASTR + c0c) * 2, A + (size_t)(m0 + r0c) * KCAT + c0c);
        cp16(sBb + (uint32_t)(r0c * ASTR + c0c) * 2, W + (size_t)(wrow0 + r0c) * KCAT + c0c);
        cp16(sAb + (uint32_t)(r1c * ASTR + c1c) * 2, A + (size_t)(m0 + r1c) * KCAT + c1c);
        cp16(sBb + (uint32_t)(r1c * ASTR + c1c) * 2, W + (size_t)(wrow0 + r1c) * KCAT + c1c);
        asm volatile("cp.async.commit_group;" ::: "memory");
    }

    for (int k = 0; k < nk; k++) {
        const int s = k & 1;
        if (k + 1 < nk) {
            const int sn = (k + 1) & 1;
            const int kof = (k + 1) * BK;
            const uint32_t so = (uint32_t)(sn * 128 * ASTR) * 2;
            cp16(sAb + so + (uint32_t)(r0c * ASTR + c0c) * 2, A + (size_t)(m0 + r0c) * KCAT + kof + c0c);
            cp16(sBb + so + (uint32_t)(r0c * ASTR + c0c) * 2, W + (size_t)(wrow0 + r0c) * KCAT + kof + c0c);
            cp16(sAb + so + (uint32_t)(r1c * ASTR + c1c) * 2, A + (size_t)(m0 + r1c) * KCAT + kof + c1c);
            cp16(sBb + so + (uint32_t)(r1c * ASTR + c1c) * 2, W + (size_t)(wrow0 + r1c) * KCAT + kof + c1c);
            asm volatile("cp.async.commit_group;" ::: "memory");
            asm volatile("cp.async.wait_group 1;" ::: "memory");
        } else {
            asm volatile("cp.async.wait_group 0;" ::: "memory");
        }
        __syncthreads();

        const uint32_t sbase = (uint32_t)(s * 128 * ASTR) * 2;
#pragma unroll
        for (int kk = 0; kk < BK; kk += 16) {
            // A fragments: 2 m-tiles of m16k16 (row-major, non-trans ldmatrix)
            uint32_t af[2][4];
#pragma unroll
            for (int mt = 0; mt < 2; mt++) {
                int row = wm * 32 + mt * 16 + (lane & 15);
                int col = kk + (lane >> 4) * 8;
                ldm_x4(af[mt], sAb + sbase + (uint32_t)(row * ASTR + col) * 2);
            }
            // B fragments: 8 n-tiles of k16n8.  W rows are [n][k] k-contiguous ->
            // B "col-major" operand loads with NON-trans ldmatrix:
            //   quads: (n-grp0,kk), (n-grp0,kk+8), (n-grp1,kk), (n-grp1,kk+8)
            uint32_t bf[8][2];
#pragma unroll
            for (int np = 0; np < 4; np++) {
                int nrow = wn * 64 + np * 16 + ((lane >> 4) << 3) + (lane & 7);
                int kcol = kk + ((lane >> 3) & 1) * 8;
                uint32_t r[4];
                ldm_x4(r, sBb + sbase + (uint32_t)(nrow * ASTR + kcol) * 2);
                bf[np * 2 + 0][0] = r[0]; bf[np * 2 + 0][1] = r[1];
                bf[np * 2 + 1][0] = r[2]; bf[np * 2 + 1][1] = r[3];
            }
#pragma unroll
            for (int mt = 0; mt < 2; mt++)
#pragma unroll
                for (int nt = 0; nt < 8; nt++)
                    mma16816(acc[mt][nt], af[mt], bf[nt]);
        }
        __syncthreads();
    }

    // ---- epilogue: fp32 stores ----
#pragma unroll
    for (int mt = 0; mt < 2; mt++) {
        int row = m0 + wm * 32 + mt * 16 + (lane >> 2);
#pragma unroll
        for (int nt = 0; nt < 8; nt++) {
            int col = n0 + wn * 64 + nt * 8 + (lane & 3) * 2;
            *(float2*)&C[(size_t)row * 1024 + col]       = make_float2(acc[mt][nt][0], acc[mt][nt][1]);
            *(float2*)&C[(size_t)(row + 8) * 1024 + col] = make_float2(acc[mt][nt][2], acc[mt][nt][3]);
        }
    }
}

// ---------------- Flash attention v2 (fp32, register-blocked outer products) ----------------
#define FQT  128
#define FKT  64
#define QSTR 132
#define KSTR 68
#define FLASH_SMEM ((2 * 64 * QSTR + 2 * 64 * KSTR) * 4)

__global__ __launch_bounds__(512) void flash_fwd2(
    const float* __restrict__ Q, const float* __restrict__ K, const float* __restrict__ V,
    float* __restrict__ O, const int* __restrict__ causalp, int S)
{
    extern __shared__ float sm[];
    float* Qs = sm;
    float* Ks = Qs + 64 * QSTR;
    float* Vs = Ks + 64 * KSTR;
    float* Ps = Vs + 64 * KSTR;

    const int qt = blockIdx.x;
    const int h  = blockIdx.y;
    const int b  = blockIdx.z;
    const int t  = threadIdx.x;
    const int tx = t & 15;
    const int ty = t >> 4;
    const int causal = causalp[0];

    const size_t base = (size_t)b * S * D_MODEL + h * HDIM;
    const int q0 = qt * FQT;

#pragma unroll
    for (int q = 0; q < 4; q++) {
        int fi = t + 512 * q;
        int r  = fi >> 4;
        int c4 = fi & 15;
        float4 v = *(const float4*)(Q + base + (size_t)(q0 + r) * D_MODEL + c4 * 4);
        Qs[(c4 * 4 + 0) * QSTR + r] = v.x * 0.125f;
        Qs[(c4 * 4 + 1) * QSTR + r] = v.y * 0.125f;
        Qs[(c4 * 4 + 2) * QSTR + r] = v.z * 0.125f;
        Qs[(c4 * 4 + 3) * QSTR + r] = v.w * 0.125f;
    }

    float o[4][4];
#pragma unroll
    for (int i = 0; i < 4; i++)
#pragma unroll
        for (int j = 0; j < 4; j++) o[i][j] = 0.f;
    float mrun[4], lrun[4];
#pragma unroll
    for (int i = 0; i < 4; i++) { mrun[i] = -CUDART_INF_F; lrun[i] = 0.f; }

    const int ntot = S >> 6;
    const int nkt  = causal ? min(ntot, 2 * qt + 2) : ntot;

    const int pr0 = t >> 4;
    const int pc0 = t & 15;
    float4 kreg[2], vreg[2];
    {
        size_t g0 = base + (size_t)(pr0) * D_MODEL + pc0 * 4;
        size_t g1 = base + (size_t)(pr0 + 32) * D_MODEL + pc0 * 4;
        kreg[0] = *(const float4*)(K + g0);
        vreg[0] = *(const float4*)(V + g0);
        kreg[1] = *(const float4*)(K + g1);
        vreg[1] = *(const float4*)(V + g1);
    }

    for (int kt = 0; kt < nkt; kt++) {
        const int k0 = kt * FKT;
#pragma unroll
        for (int q = 0; q < 2; q++) {
            int r  = pr0 + 32 * q;
            int d0 = pc0 * 4;
            Ks[(d0 + 0) * KSTR + r] = (q ? kreg[1].x : kreg[0].x);
            Ks[(d0 + 1) * KSTR + r] = (q ? kreg[1].y : kreg[0].y);
            Ks[(d0 + 2) * KSTR + r] = (q ? kreg[1].z : kreg[0].z);
            Ks[(d0 + 3) * KSTR + r] = (q ? kreg[1].w : kreg[0].w);
            *(float4*)&Vs[r * KSTR + d0] = (q ? vreg[1] : vreg[0]);
        }
        __syncthreads();

        if (kt + 1 < nkt) {
            size_t g0 = base + (size_t)(k0 + FKT + pr0) * D_MODEL + pc0 * 4;
            size_t g1 = base + (size_t)(k0 + FKT + pr0 + 32) * D_MODEL + pc0 * 4;
            kreg[0] = *(const float4*)(K + g0);
            vreg[0] = *(const float4*)(V + g0);
            kreg[1] = *(const float4*)(K + g1);
            vreg[1] = *(const float4*)(V + g1);
        }

        float s[4][4];
#pragma unroll
        for (int i = 0; i < 4; i++)
#pragma unroll
            for (int j = 0; j < 4; j++) s[i][j] = 0.f;

#pragma unroll 8
        for (int d = 0; d < 64; d++) {
            float4 a  = *(const float4*)&Qs[d * QSTR + ty * 4];
            float4 bb = *(const float4*)&Ks[d * KSTR + tx * 4];
            s[0][0] += a.x * bb.x; s[0][1] += a.x * bb.y; s[0][2] += a.x * bb.z; s[0][3] += a.x * bb.w;
            s[1][0] += a.y * bb.x; s[1][1] += a.y * bb.y; s[1][2] += a.y * bb.z; s[1][3] += a.y * bb.w;
            s[2][0] += a.z * bb.x; s[2][1] += a.z * bb.y; s[2][2] += a.z * bb.z; s[2][3] += a.z * bb.w;
            s[3][0] += a.w * bb.x; s[3][1] += a.w * bb.y; s[3][2] += a.w * bb.z; s[3][3] += a.w * bb.w;
        }

        if (causal && (k0 + FKT - 1 > q0 + ty * 4)) {
#pragma unroll
            for (int i = 0; i < 4; i++) {
                int qg = q0 + ty * 4 + i;
#pragma unroll
                for (int j = 0; j < 4; j++) {
                    if (k0 + tx * 4 + j > qg) s[i][j] = -CUDART_INF_F;
                }
            }
        }

#pragma unroll
        for (int i = 0; i < 4; i++) {
            float mloc = fmaxf(fmaxf(s[i][0], s[i][1]), fmaxf(s[i][2], s[i][3]));
            mloc = fmaxf(mloc, __shfl_xor_sync(0xffffffffu, mloc, 1, 16));
            mloc = fmaxf(mloc, __shfl_xor_sync(0xffffffffu, mloc, 2, 16));
            mloc = fmaxf(mloc, __shfl_xor_sync(0xffffffffu, mloc, 4, 16));
            mloc = fmaxf(mloc, __shfl_xor_sync(0xffffffffu, mloc, 8, 16));
            float mnew = fmaxf(mrun[i], mloc);
            float corr = __expf(mrun[i] - mnew);
            float p0 = __expf(s[i][0] - mnew);
            float p1 = __expf(s[i][1] - mnew);
            float p2 = __expf(s[i][2] - mnew);
            float p3 = __expf(s[i][3] - mnew);
            s[i][0] = p0; s[i][1] = p1; s[i][2] = p2; s[i][3] = p3;
            float ls = p0 + p1 + p2 + p3;
            ls += __shfl_xor_sync(0xffffffffu, ls, 1, 16);
            ls += __shfl_xor_sync(0xffffffffu, ls, 2, 16);
            ls += __shfl_xor_sync(0xffffffffu, ls, 4, 16);
            ls += __shfl_xor_sync(0xffffffffu, ls, 8, 16);
            lrun[i] = lrun[i] * corr + ls;
            mrun[i] = mnew;
            o[i][0] *= corr; o[i][1] *= corr; o[i][2] *= corr; o[i][3] *= corr;
        }

#pragma unroll
        for (int j = 0; j < 4; j++) {
            *(float4*)&Ps[(tx * 4 + j) * QSTR + ty * 4] =
                make_float4(s[0][j], s[1][j], s[2][j], s[3][j]);
        }
        __syncthreads();

#pragma unroll 8
        for (int j = 0; j < 64; j++) {
            float4 a  = *(const float4*)&Ps[j * QSTR + ty * 4];
            float4 v4 = *(const float4*)&Vs[j * KSTR + tx * 4];
            o[0][0] += a.x * v4.x; o[0][1] += a.x * v4.y; o[0][2] += a.x * v4.z; o[0][3] += a.x * v4.w;
            o[1][0] += a.y * v4.x; o[1][1] += a.y * v4.y; o[1][2] += a.y * v4.z; o[1][3] += a.y * v4.w;
            o[2][0] += a.z * v4.x; o[2][1] += a.z * v4.y; o[2][2] += a.z * v4.z; o[2][3] += a.z * v4.w;
            o[3][0] += a.w * v4.x; o[3][1] += a.w * v4.y; o[3][2] += a.w * v4.z; o[3][3] += a.w * v4.w;
        }
        __syncthreads();
    }

#pragma unroll
    for (int i = 0; i < 4; i++) {
        float inv = 1.f / lrun[i];
        float* op = O + base + (size_t)(q0 + ty * 4 + i) * D_MODEL + tx * 4;
        *(float4*)op = make_float4(o[i][0] * inv, o[i][1] * inv, o[i][2] * inv, o[i][3] * inv);
    }
}

// ---------------- launch ----------------
extern "C" void kernel_launch(void* const* d_in, const int* in_sizes, int n_in,
                              void* d_out, int out_size)
{
    const float* x  = (const float*)d_in[0];
    const float* Wq = (const float*)d_in[1];
    const float* Wk = (const float*)d_in[2];
    const float* Wv = (const float*)d_in[3];
    const float* Wo = (const float*)d_in[4];
    const int*   causal = (const int*)d_in[5];

    const int BS = in_sizes[0] / D_MODEL;   // 4096
    const int S  = 2048;
    const int B  = BS / S;

    float *qb, *kb, *vb, *ob;
    __nv_bfloat16 *xcat, *wcat, *ocat;
    cudaGetSymbolAddress((void**)&qb, g_Q);
    cudaGetSymbolAddress((void**)&kb, g_K);
    cudaGetSymbolAddress((void**)&vb, g_V);
    cudaGetSymbolAddress((void**)&ob, g_Oa);
    cudaGetSymbolAddress((void**)&xcat, g_Xcat);
    cudaGetSymbolAddress((void**)&wcat, g_Wcat);
    cudaGetSymbolAddress((void**)&ocat, g_Ocat);

    cudaFuncSetAttribute(flash_fwd2, cudaFuncAttributeMaxDynamicSharedMemorySize, FLASH_SMEM);

    // ---- convert x and all four weights to bf16 split-cat ----
    convert_split<<<(BS * 256) / 256, 256>>>(x, xcat, 0);
    convert_split<<<1024, 256>>>(Wq, wcat + (size_t)0 * 1024 * KCAT, 1);
    convert_split<<<1024, 256>>>(Wk, wcat + (size_t)1 * 1024 * KCAT, 1);
    convert_split<<<1024, 256>>>(Wv, wcat + (size_t)2 * 1024 * KCAT, 1);
    convert_split<<<1024, 256>>>(Wo, wcat + (size_t)3 * 1024 * KCAT, 1);

    // ---- Q/K/V projections on mma.sync (HMMA) ----
    gemm_mma<<<dim3(D_MODEL / 128, BS / 128, 3), 256>>>(xcat, wcat, qb, kb, vb, 0);

    // ---- flash attention (fp32 SIMT) ----
    dim3 gfl(S / FQT, NHEAD, B);
    flash_fwd2<<<gfl, 512, FLASH_SMEM>>>(qb, kb, vb, ob, causal, S);

    // ---- output projection on mma.sync ----
    convert_split<<<(BS * 256) / 256, 256>>>(ob, ocat, 0);
    gemm_mma<<<dim3(D_MODEL / 128, BS / 128, 1), 256>>>(
        ocat, wcat, (float*)d_out, (float*)d_out, (float*)d_out, 3 * 1024);
}

// round 12
// speedup vs baseline: 6.8514x; 1.7412x over previous
#include <cuda_runtime.h>
#include <cuda_bf16.h>
#include <math_constants.h>
#include <cstdint>

// Problem constants (fixed by setup_inputs)
#define D_MODEL 1024
#define NHEAD   16
#define HDIM    64
#define KCAT    3072          // 3 * D_MODEL (bf16-split: A=[hi,hi,lo], W=[hi,lo,hi])

// ---------------- scratch (no allocations allowed) ----------------
__device__ __nv_bfloat16 g_Xcat[4096 * KCAT];
__device__ __nv_bfloat16 g_Wcat[4096 * KCAT];   // 4 weights stacked (q,k,v,o)
__device__ __nv_bfloat16 g_Ocat[4096 * KCAT];   // attention out, split-cat [hi,hi,lo]
__device__ __nv_bfloat16 g_Qh[4096 * 1024], g_Ql[4096 * 1024];
__device__ __nv_bfloat16 g_Kh[4096 * 1024], g_Kl[4096 * 1024];
__device__ __nv_bfloat16 g_Vh[4096 * 1024], g_Vl[4096 * 1024];

// =================== small PTX helpers (plain sm_80/90 features only) ===================
__device__ __forceinline__ uint32_t smem_u32(const void* p) {
    uint32_t a;
    asm("{ .reg .u64 t; cvta.to.shared.u64 t, %1; cvt.u32.u64 %0, t; }" : "=r"(a) : "l"(p));
    return a;
}
__device__ __forceinline__ void cp16(uint32_t dst, const void* src) {
    asm volatile("cp.async.cg.shared.global [%0], [%1], 16;" :: "r"(dst), "l"(src) : "memory");
}
__device__ __forceinline__ void ldm_x4(uint32_t* r, uint32_t addr) {
    asm volatile("ldmatrix.sync.aligned.m8n8.x4.shared.b16 {%0,%1,%2,%3}, [%4];"
                 : "=r"(r[0]), "=r"(r[1]), "=r"(r[2]), "=r"(r[3]) : "r"(addr));
}
__device__ __forceinline__ void ldm_x4_t(uint32_t* r, uint32_t addr) {
    asm volatile("ldmatrix.sync.aligned.m8n8.x4.trans.shared.b16 {%0,%1,%2,%3}, [%4];"
                 : "=r"(r[0]), "=r"(r[1]), "=r"(r[2]), "=r"(r[3]) : "r"(addr));
}
__device__ __forceinline__ void mma16816(float* d, const uint32_t* a, const uint32_t* b) {
    asm volatile(
        "mma.sync.aligned.m16n8k16.row.col.f32.bf16.bf16.f32 "
        "{%0,%1,%2,%3}, {%4,%5,%6,%7}, {%8,%9}, {%0,%1,%2,%3};"
        : "+f"(d[0]), "+f"(d[1]), "+f"(d[2]), "+f"(d[3])
        : "r"(a[0]), "r"(a[1]), "r"(a[2]), "r"(a[3]), "r"(b[0]), "r"(b[1]));
}
__device__ __forceinline__ uint32_t pk2(__nv_bfloat16 a, __nv_bfloat16 b) {
    return (uint32_t)__bfloat16_as_ushort(a) | ((uint32_t)__bfloat16_as_ushort(b) << 16);
}
__device__ __forceinline__ void split2(float a, float b, uint32_t& hp, uint32_t& lp) {
    __nv_bfloat16 ha = __float2bfloat16(a), hb = __float2bfloat16(b);
    __nv_bfloat16 la = __float2bfloat16(a - __bfloat162float(ha));
    __nv_bfloat16 lb = __float2bfloat16(b - __bfloat162float(hb));
    hp = pk2(ha, hb); lp = pk2(la, lb);
}

// =================== fp32 -> bf16 hi/lo split-cat conversion ===================
// src [rows,1024] fp32 -> dst [rows,3072] bf16.  mode 0 (A): [hi,hi,lo]; mode 1 (W): [hi,lo,hi]
__global__ __launch_bounds__(256) void convert_split(
    const float* __restrict__ src, __nv_bfloat16* __restrict__ dst, int mode)
{
    int i4 = blockIdx.x * blockDim.x + threadIdx.x;
    float4 v = ((const float4*)src)[i4];
    int row = i4 >> 8;
    int c   = (i4 & 255) * 4;
    float f[4] = {v.x, v.y, v.z, v.w};
    __nv_bfloat16 h[4], l[4];
#pragma unroll
    for (int i = 0; i < 4; i++) {
        h[i] = __float2bfloat16(f[i]);
        l[i] = __float2bfloat16(f[i] - __bfloat162float(h[i]));
    }
    uint2 hp = make_uint2(pk2(h[0], h[1]), pk2(h[2], h[3]));
    uint2 lp = make_uint2(pk2(l[0], l[1]), pk2(l[2], l[3]));
    size_t b = (size_t)row * KCAT + c;
    *(uint2*)&dst[b]        = hp;
    *(uint2*)&dst[b + 1024] = mode ? lp : hp;
    *(uint2*)&dst[b + 2048] = mode ? hp : lp;
}

// =================== mma.sync bf16 GEMM: C[M,1024] = A_cat[M,3072] @ W_cat^T ===================
// 128x128 tile, BK=32, 256 threads (8 warps in 4x2). mode 0: fp32 out. mode 1: bf16 hi/lo
// split outputs per z (z==0 also scales by 0.125 for Q).
#define BK    32
#define ASTR  40
#define NSTG  2

__global__ __launch_bounds__(256) void gemm_mma(
    const __nv_bfloat16* __restrict__ A, const __nv_bfloat16* __restrict__ W,
    int wbase, int mode, float* __restrict__ Cf,
    __nv_bfloat16* __restrict__ H0, __nv_bfloat16* __restrict__ L0,
    __nv_bfloat16* __restrict__ H1, __nv_bfloat16* __restrict__ L1,
    __nv_bfloat16* __restrict__ H2, __nv_bfloat16* __restrict__ L2)
{
    __shared__ __nv_bfloat16 sA[NSTG][128 * ASTR];
    __shared__ __nv_bfloat16 sB[NSTG][128 * ASTR];

    const int z  = blockIdx.z;
    const int m0 = blockIdx.y * 128;
    const int n0 = blockIdx.x * 128;
    const int wrow0 = wbase + z * 1024 + n0;

    const int t    = threadIdx.x;
    const int lane = t & 31;
    const int wid  = t >> 5;
    const int wm   = wid & 3;
    const int wn   = wid >> 2;

    const uint32_t sAb = smem_u32(sA);
    const uint32_t sBb = smem_u32(sB);

    const int r0c = t >> 2, c0c = (t & 3) * 8;
    const int r1c = (t + 256) >> 2, c1c = ((t + 256) & 3) * 8;

    float acc[2][8][4];
#pragma unroll
    for (int mt = 0; mt < 2; mt++)
#pragma unroll
        for (int nt = 0; nt < 8; nt++)
#pragma unroll
            for (int q = 0; q < 4; q++) acc[mt][nt][q] = 0.f;

    const int nk = KCAT / BK;

    {
        cp16(sAb + (uint32_t)(r0c * ASTR + c0c) * 2, A + (size_t)(m0 + r0c) * KCAT + c0c);
        cp16(sBb + (uint32_t)(r0c * ASTR + c0c) * 2, W + (size_t)(wrow0 + r0c) * KCAT + c0c);
        cp16(sAb + (uint32_t)(r1c * ASTR + c1c) * 2, A + (size_t)(m0 + r1c) * KCAT + c1c);
        cp16(sBb + (uint32_t)(r1c * ASTR + c1c) * 2, W + (size_t)(wrow0 + r1c) * KCAT + c1c);
        asm volatile("cp.async.commit_group;" ::: "memory");
    }

    for (int k = 0; k < nk; k++) {
        const int s = k & 1;
        if (k + 1 < nk) {
            const int sn = (k + 1) & 1;
            const int kof = (k + 1) * BK;
            const uint32_t so = (uint32_t)(sn * 128 * ASTR) * 2;
            cp16(sAb + so + (uint32_t)(r0c * ASTR + c0c) * 2, A + (size_t)(m0 + r0c) * KCAT + kof + c0c);
            cp16(sBb + so + (uint32_t)(r0c * ASTR + c0c) * 2, W + (size_t)(wrow0 + r0c) * KCAT + kof + c0c);
            cp16(sAb + so + (uint32_t)(r1c * ASTR + c1c) * 2, A + (size_t)(m0 + r1c) * KCAT + kof + c1c);
            cp16(sBb + so + (uint32_t)(r1c * ASTR + c1c) * 2, W + (size_t)(wrow0 + r1c) * KCAT + kof + c1c);
            asm volatile("cp.async.commit_group;" ::: "memory");
            asm volatile("cp.async.wait_group 1;" ::: "memory");
        } else {
            asm volatile("cp.async.wait_group 0;" ::: "memory");
        }
        __syncthreads();

        const uint32_t sbase = (uint32_t)(s * 128 * ASTR) * 2;
#pragma unroll
        for (int kk = 0; kk < BK; kk += 16) {
            uint32_t af[2][4];
#pragma unroll
            for (int mt = 0; mt < 2; mt++) {
                int row = wm * 32 + mt * 16 + (lane & 15);
                int col = kk + (lane >> 4) * 8;
                ldm_x4(af[mt], sAb + sbase + (uint32_t)(row * ASTR + col) * 2);
            }
            uint32_t bf[8][2];
#pragma unroll
            for (int np = 0; np < 4; np++) {
                int nrow = wn * 64 + np * 16 + ((lane >> 4) << 3) + (lane & 7);   // FIX: restore wn*64
                int kcol = kk + ((lane >> 3) & 1) * 8;
                uint32_t r[4];
                ldm_x4(r, sBb + sbase + (uint32_t)(nrow * ASTR + kcol) * 2);
                bf[np * 2 + 0][0] = r[0]; bf[np * 2 + 0][1] = r[1];
                bf[np * 2 + 1][0] = r[2]; bf[np * 2 + 1][1] = r[3];
            }
#pragma unroll
            for (int mt = 0; mt < 2; mt++)
#pragma unroll
                for (int nt = 0; nt < 8; nt++)
                    mma16816(acc[mt][nt], af[mt], bf[nt]);
        }
        __syncthreads();
    }

    if (mode == 0) {
#pragma unroll
        for (int mt = 0; mt < 2; mt++) {
            int row = m0 + wm * 32 + mt * 16 + (lane >> 2);
#pragma unroll
            for (int nt = 0; nt < 8; nt++) {
                int col = n0 + wn * 64 + nt * 8 + (lane & 3) * 2;
                *(float2*)&Cf[(size_t)row * 1024 + col]       = make_float2(acc[mt][nt][0], acc[mt][nt][1]);
                *(float2*)&Cf[(size_t)(row + 8) * 1024 + col] = make_float2(acc[mt][nt][2], acc[mt][nt][3]);
            }
        }
    } else {
        __nv_bfloat16* Ch = (z == 0) ? H0 : (z == 1) ? H1 : H2;
        __nv_bfloat16* Cl = (z == 0) ? L0 : (z == 1) ? L1 : L2;
        const float sc = (z == 0) ? 0.125f : 1.0f;   // fold 1/sqrt(Hd) into Q
#pragma unroll
        for (int mt = 0; mt < 2; mt++) {
            int row = m0 + wm * 32 + mt * 16 + (lane >> 2);
#pragma unroll
            for (int nt = 0; nt < 8; nt++) {
                int col = n0 + wn * 64 + nt * 8 + (lane & 3) * 2;
                uint32_t hp, lp;
                split2(acc[mt][nt][0] * sc, acc[mt][nt][1] * sc, hp, lp);
                *(uint32_t*)&Ch[(size_t)row * 1024 + col] = hp;
                *(uint32_t*)&Cl[(size_t)row * 1024 + col] = lp;
                split2(acc[mt][nt][2] * sc, acc[mt][nt][3] * sc, hp, lp);
                *(uint32_t*)&Ch[(size_t)(row + 8) * 1024 + col] = hp;
                *(uint32_t*)&Cl[(size_t)(row + 8) * 1024 + col] = lp;
            }
        }
    }
}

// =================== Flash attention v3: mma.sync bf16 3-split ===================
// Block: 128 q-rows x 64 k-tile, 256 threads = 8 warps (m16 each).
// Smem bf16 stride 72 (rows 144B apart -> conflict-free ldmatrix).
#define FSTR3 72
#define QH_OFF 0
#define QL_OFF (128 * FSTR3)
#define ST_OFF(s) (2 * 128 * FSTR3 + (s) * (4 * 64 * FSTR3))
#define KH_OFF 0
#define KL_OFF (64 * FSTR3)
#define VH_OFF (2 * 64 * FSTR3)
#define VL_OFF (3 * 64 * FSTR3)
#define FLASH3_SMEM ((2 * 128 * FSTR3 + 2 * 4 * 64 * FSTR3) * 2)   // 110,592 B

__global__ __launch_bounds__(256) void flash_fwd3(
    const __nv_bfloat16* __restrict__ Qh, const __nv_bfloat16* __restrict__ Ql,
    const __nv_bfloat16* __restrict__ Kh, const __nv_bfloat16* __restrict__ Kl,
    const __nv_bfloat16* __restrict__ Vh, const __nv_bfloat16* __restrict__ Vl,
    __nv_bfloat16* __restrict__ Ocat, const int* __restrict__ causalp, int S)
{
    extern __shared__ __nv_bfloat16 smem3[];
    const uint32_t sb = smem_u32(smem3);

    const int qt = gridDim.x - 1 - blockIdx.x;   // heavy (large-qt) blocks first
    const int h  = blockIdx.y;
    const int b  = blockIdx.z;
    const int t  = threadIdx.x;
    const int lane = t & 31;
    const int wid  = t >> 5;
    const int wq   = wid * 16;
    const int causal = causalp[0];

    const int q0 = qt * 128;
    const size_t tok0 = (size_t)b * S;
    const size_t colh = (size_t)h * HDIM;

    // ---- prologue: Q tiles + k-tile 0 via cp.async ----
#pragma unroll
    for (int c = 0; c < 4; c++) {
        int ci = t + 256 * c;            // 0..1023 chunks of 8 bf16
        int row = ci >> 3, col8 = (ci & 7) * 8;
        const __nv_bfloat16* gq = Qh + (tok0 + q0 + row) * D_MODEL + colh + col8;
        const __nv_bfloat16* gl = Ql + (tok0 + q0 + row) * D_MODEL + colh + col8;
        cp16(sb + (uint32_t)(QH_OFF + row * FSTR3 + col8) * 2, gq);
        cp16(sb + (uint32_t)(QL_OFF + row * FSTR3 + col8) * 2, gl);
    }
    const int ntot = S >> 6;
    const int nkt  = causal ? min(ntot, 2 * qt + 2) : ntot;
    {
#pragma unroll
        for (int c = 0; c < 2; c++) {
            int ci = t + 256 * c;        // 0..511
            int row = ci >> 3, col8 = (ci & 7) * 8;
            size_t g = (tok0 + row) * D_MODEL + colh + col8;
            uint32_t d = (uint32_t)(ST_OFF(0) + row * FSTR3 + col8) * 2;
            cp16(sb + d + KH_OFF * 2, Kh + g);
            cp16(sb + d + KL_OFF * 2, Kl + g);
            cp16(sb + d + VH_OFF * 2, Vh + g);
            cp16(sb + d + VL_OFF * 2, Vl + g);
        }
        asm volatile("cp.async.commit_group;" ::: "memory");
    }

    float sacc[8][4], oacc[8][4];
#pragma unroll
    for (int nt = 0; nt < 8; nt++)
#pragma unroll
        for (int q = 0; q < 4; q++) oacc[nt][q] = 0.f;
    float mrun0 = -CUDART_INF_F, mrun1 = -CUDART_INF_F, lrun0 = 0.f, lrun1 = 0.f;

    for (int kt = 0; kt < nkt; kt++) {
        const int s  = kt & 1;
        const int k0 = kt * 64;
        if (kt + 1 < nkt) {
            const int sn = (kt + 1) & 1;
#pragma unroll
            for (int c = 0; c < 2; c++) {
                int ci = t + 256 * c;
                int row = ci >> 3, col8 = (ci & 7) * 8;
                size_t g = (tok0 + k0 + 64 + row) * D_MODEL + colh + col8;
                uint32_t d = (uint32_t)(ST_OFF(sn) + row * FSTR3 + col8) * 2;
                cp16(sb + d + KH_OFF * 2, Kh + g);
                cp16(sb + d + KL_OFF * 2, Kl + g);
                cp16(sb + d + VH_OFF * 2, Vh + g);
                cp16(sb + d + VL_OFF * 2, Vl + g);
            }
            asm volatile("cp.async.commit_group;" ::: "memory");
            asm volatile("cp.async.wait_group 1;" ::: "memory");
        } else {
            asm volatile("cp.async.wait_group 0;" ::: "memory");
        }
        __syncthreads();

        const uint32_t kbase = sb + (uint32_t)ST_OFF(s) * 2;

        // ---- S = Q K^T (3-term split), per warp 16q x 64k ----
#pragma unroll
        for (int nt = 0; nt < 8; nt++)
#pragma unroll
            for (int q = 0; q < 4; q++) sacc[nt][q] = 0.f;

#pragma unroll
        for (int kk = 0; kk < 64; kk += 16) {
            uint32_t ah[4], al[4];
            {
                int row = wq + (lane & 15);
                int col = kk + (lane >> 4) * 8;
                ldm_x4(ah, sb + (uint32_t)(QH_OFF + row * FSTR3 + col) * 2);
                ldm_x4(al, sb + (uint32_t)(QL_OFF + row * FSTR3 + col) * 2);
            }
            uint32_t bh[8][2], bl[8][2];
#pragma unroll
            for (int np = 0; np < 4; np++) {
                int nrow = np * 16 + ((lane >> 4) << 3) + (lane & 7);
                int kcol = kk + ((lane >> 3) & 1) * 8;
                uint32_t r[4];
                ldm_x4(r, kbase + (uint32_t)(KH_OFF + nrow * FSTR3 + kcol) * 2);
                bh[np * 2 + 0][0] = r[0]; bh[np * 2 + 0][1] = r[1];
                bh[np * 2 + 1][0] = r[2]; bh[np * 2 + 1][1] = r[3];
                ldm_x4(r, kbase + (uint32_t)(KL_OFF + nrow * FSTR3 + kcol) * 2);
                bl[np * 2 + 0][0] = r[0]; bl[np * 2 + 0][1] = r[1];
                bl[np * 2 + 1][0] = r[2]; bl[np * 2 + 1][1] = r[3];
            }
#pragma unroll
            for (int nt = 0; nt < 8; nt++) {
                mma16816(sacc[nt], ah, bh[nt]);
                mma16816(sacc[nt], ah, bl[nt]);
                mma16816(sacc[nt], al, bh[nt]);
            }
        }

        // ---- causal mask ----
        if (causal && (k0 + 63 > q0 + wq)) {
            int qg0 = q0 + wq + (lane >> 2);
#pragma unroll
            for (int nt = 0; nt < 8; nt++) {
                int kg = k0 + nt * 8 + (lane & 3) * 2;
                if (kg     > qg0)     sacc[nt][0] = -CUDART_INF_F;
                if (kg + 1 > qg0)     sacc[nt][1] = -CUDART_INF_F;
                if (kg     > qg0 + 8) sacc[nt][2] = -CUDART_INF_F;
                if (kg + 1 > qg0 + 8) sacc[nt][3] = -CUDART_INF_F;
            }
        }

        // ---- online softmax (rows r0 = lane>>2, r1 = r0+8; quad = 4 lanes/row) ----
        {
            float m0 = sacc[0][0], m1 = sacc[0][2];
#pragma unroll
            for (int nt = 0; nt < 8; nt++) {
                m0 = fmaxf(m0, fmaxf(sacc[nt][0], sacc[nt][1]));
                m1 = fmaxf(m1, fmaxf(sacc[nt][2], sacc[nt][3]));
            }
            m0 = fmaxf(m0, __shfl_xor_sync(0xffffffffu, m0, 1));
            m0 = fmaxf(m0, __shfl_xor_sync(0xffffffffu, m0, 2));
            m1 = fmaxf(m1, __shfl_xor_sync(0xffffffffu, m1, 1));
            m1 = fmaxf(m1, __shfl_xor_sync(0xffffffffu, m1, 2));
            float mn0 = fmaxf(mrun0, m0), mn1 = fmaxf(mrun1, m1);
            float cr0 = __expf(mrun0 - mn0), cr1 = __expf(mrun1 - mn1);
            float ls0 = 0.f, ls1 = 0.f;
#pragma unroll
            for (int nt = 0; nt < 8; nt++) {
                sacc[nt][0] = __expf(sacc[nt][0] - mn0);
                sacc[nt][1] = __expf(sacc[nt][1] - mn0);
                sacc[nt][2] = __expf(sacc[nt][2] - mn1);
                sacc[nt][3] = __expf(sacc[nt][3] - mn1);
                ls0 += sacc[nt][0] + sacc[nt][1];
                ls1 += sacc[nt][2] + sacc[nt][3];
            }
            ls0 += __shfl_xor_sync(0xffffffffu, ls0, 1);
            ls0 += __shfl_xor_sync(0xffffffffu, ls0, 2);
            ls1 += __shfl_xor_sync(0xffffffffu, ls1, 1);
            ls1 += __shfl_xor_sync(0xffffffffu, ls1, 2);
            lrun0 = lrun0 * cr0 + ls0;  mrun0 = mn0;
            lrun1 = lrun1 * cr1 + ls1;  mrun1 = mn1;
#pragma unroll
            for (int nt = 0; nt < 8; nt++) {
                oacc[nt][0] *= cr0; oacc[nt][1] *= cr0;
                oacc[nt][2] *= cr1; oacc[nt][3] *= cr1;
            }
        }

        // ---- O += P V (3-term split); P frags direct from sacc ----
#pragma unroll
        for (int jt = 0; jt < 4; jt++) {
            uint32_t aPh[4], aPl[4];
            split2(sacc[2 * jt][0],     sacc[2 * jt][1],     aPh[0], aPl[0]);
            split2(sacc[2 * jt][2],     sacc[2 * jt][3],     aPh[1], aPl[1]);
            split2(sacc[2 * jt + 1][0], sacc[2 * jt + 1][1], aPh[2], aPl[2]);
            split2(sacc[2 * jt + 1][2], sacc[2 * jt + 1][3], aPh[3], aPl[3]);

            uint32_t vh[8][2], vl[8][2];
#pragma unroll
            for (int dp = 0; dp < 4; dp++) {
                int vrow = jt * 16 + (lane & 15);
                int vcol = dp * 16 + (lane >> 4) * 8;
                uint32_t r[4];
                ldm_x4_t(r, kbase + (uint32_t)(VH_OFF + vrow * FSTR3 + vcol) * 2);
                vh[dp * 2 + 0][0] = r[0]; vh[dp * 2 + 0][1] = r[1];
                vh[dp * 2 + 1][0] = r[2]; vh[dp * 2 + 1][1] = r[3];
                ldm_x4_t(r, kbase + (uint32_t)(VL_OFF + vrow * FSTR3 + vcol) * 2);
                vl[dp * 2 + 0][0] = r[0]; vl[dp * 2 + 0][1] = r[1];
                vl[dp * 2 + 1][0] = r[2]; vl[dp * 2 + 1][1] = r[3];
            }
#pragma unroll
            for (int nt = 0; nt < 8; nt++) {
                mma16816(oacc[nt], aPh, vh[nt]);
                mma16816(oacc[nt], aPh, vl[nt]);
                mma16816(oacc[nt], aPl, vh[nt]);
            }
        }
        __syncthreads();
    }

    // ---- epilogue: normalize, write split-cat [hi,hi,lo] into Ocat ----
    {
        float inv0 = 1.f / lrun0, inv1 = 1.f / lrun1;
        size_t r0 = tok0 + q0 + wq + (lane >> 2);
        size_t r1 = r0 + 8;
#pragma unroll
        for (int nt = 0; nt < 8; nt++) {
            size_t col = colh + nt * 8 + (lane & 3) * 2;
            uint32_t hp, lp;
            split2(oacc[nt][0] * inv0, oacc[nt][1] * inv0, hp, lp);
            *(uint32_t*)&Ocat[r0 * KCAT + col]        = hp;
            *(uint32_t*)&Ocat[r0 * KCAT + col + 1024] = hp;
            *(uint32_t*)&Ocat[r0 * KCAT + col + 2048] = lp;
            split2(oacc[nt][2] * inv1, oacc[nt][3] * inv1, hp, lp);
            *(uint32_t*)&Ocat[r1 * KCAT + col]        = hp;
            *(uint32_t*)&Ocat[r1 * KCAT + col + 1024] = hp;
            *(uint32_t*)&Ocat[r1 * KCAT + col + 2048] = lp;
        }
    }
}

// ---------------- launch ----------------
extern "C" void kernel_launch(void* const* d_in, const int* in_sizes, int n_in,
                              void* d_out, int out_size)
{
    const float* x  = (const float*)d_in[0];
    const float* Wq = (const float*)d_in[1];
    const float* Wk = (const float*)d_in[2];
    const float* Wv = (const float*)d_in[3];
    const float* Wo = (const float*)d_in[4];
    const int*   causal = (const int*)d_in[5];

    const int BS = in_sizes[0] / D_MODEL;   // 4096
    const int S  = 2048;
    const int B  = BS / S;

    __nv_bfloat16 *xcat, *wcat, *ocat, *qh, *ql, *kh, *kl, *vh, *vl;
    cudaGetSymbolAddress((void**)&xcat, g_Xcat);
    cudaGetSymbolAddress((void**)&wcat, g_Wcat);
    cudaGetSymbolAddress((void**)&ocat, g_Ocat);
    cudaGetSymbolAddress((void**)&qh, g_Qh);  cudaGetSymbolAddress((void**)&ql, g_Ql);
    cudaGetSymbolAddress((void**)&kh, g_Kh);  cudaGetSymbolAddress((void**)&kl, g_Kl);
    cudaGetSymbolAddress((void**)&vh, g_Vh);  cudaGetSymbolAddress((void**)&vl, g_Vl);

    cudaFuncSetAttribute(flash_fwd3, cudaFuncAttributeMaxDynamicSharedMemorySize, FLASH3_SMEM);

    // ---- convert x and all four weights to bf16 split-cat ----
    convert_split<<<(BS * 256) / 256, 256>>>(x, xcat, 0);
    convert_split<<<1024, 256>>>(Wq, wcat + (size_t)0 * 1024 * KCAT, 1);
    convert_split<<<1024, 256>>>(Wk, wcat + (size_t)1 * 1024 * KCAT, 1);
    convert_split<<<1024, 256>>>(Wv, wcat + (size_t)2 * 1024 * KCAT, 1);
    convert_split<<<1024, 256>>>(Wo, wcat + (size_t)3 * 1024 * KCAT, 1);

    // ---- Q/K/V projections -> bf16 hi/lo split outputs (Q pre-scaled by 0.125) ----
    gemm_mma<<<dim3(D_MODEL / 128, BS / 128, 3), 256>>>(
        xcat, wcat, 0, 1, nullptr, qh, ql, kh, kl, vh, vl);

    // ---- tensor-core flash attention -> Ocat (split-cat) ----
    dim3 gfl(S / 128, NHEAD, B);
    flash_fwd3<<<gfl, 256, FLASH3_SMEM>>>(qh, ql, kh, kl, vh, vl, ocat, causal, S);

    // ---- output projection -> fp32 d_out ----
    gemm_mma<<<dim3(D_MODEL / 128, BS / 128, 1), 256>>>(
        ocat, wcat, 3 * 1024, 0, (float*)d_out,
        nullptr, nullptr, nullptr, nullptr, nullptr, nullptr);
}